// round 16
// baseline (speedup 1.0000x reference)
#include <cuda_runtime.h>
#include <cuda_bf16.h>
#include <cstdint>

// out[b,k] = log( sum_n exp(x[b,n]) * exp(acc[n,k]) ) - log( sum_n exp(acc[n,k]) )
// per (s,d): GEMM M=128, N=512, K=512.
// Pass 1: exp(X) -> bf16 scratch.
// Pass 2: HMMA GEMM. A: 3-stage bf16 ring, W: 2-stage fp32 ring, distance-2
// issue, retire one iter before the consuming barrier. One barrier/chunk;
// convert(ch+1) overlaps MMA(ch). 4 CTAs/SM.
// R16: row-contiguous convert (1x STS.128), csum[8] + shfl reduce, tighter addr.

#define NSD     256
#define BDIM    128
#define NIN     512
#define NSUM    512
#define KC      32
#define NT      64
#define APITCH  40          // bf16/row (80B): LDSM conflict-free
#define BPITCH  72          // bf16/row (144B): LDSM conflict-free
#define NCH     (NIN/KC)    // 16
#define RINGA   3
#define RINGW   2
#define ASTG    (BDIM*APITCH*2)     // 10240 B
#define WSTG    (KC*NT*4)           // 8192 B
#define BSBUF   (KC*BPITCH*2)       // 4608 B
#define SM_A    0
#define SM_W    (RINGA*ASTG)                // 30720
#define SM_B    (SM_W + RINGW*WSTG)         // 47104
#define SM_TOT  (SM_B + 2*BSBUF)            // 56320

__device__ __nv_bfloat16 g_xe[(size_t)NSD * BDIM * NIN];   // 33.5MB scratch

__device__ __forceinline__ unsigned packbf(float a, float b) {
    __nv_bfloat162 h = __floats2bfloat162_rn(a, b);
    return *reinterpret_cast<unsigned const*>(&h);
}
__device__ __forceinline__ uint32_t s2u(const void* p) {
    uint32_t a;
    asm("{ .reg .u64 t; cvta.to.shared.u64 t, %1; cvt.u32.u64 %0, t; }" : "=r"(a) : "l"(p));
    return a;
}

// ---------------- Pass 1: Xe = bf16(exp(X)) ----------------
__global__ __launch_bounds__(256) void expx_kernel(const float* __restrict__ X) {
    const size_t i = ((size_t)blockIdx.x * blockDim.x + threadIdx.x) * 8;
    float4 a = *reinterpret_cast<const float4*>(X + i);
    float4 b = *reinterpret_cast<const float4*>(X + i + 4);
    uint4 u;
    u.x = packbf(__expf(a.x), __expf(a.y));
    u.y = packbf(__expf(a.z), __expf(a.w));
    u.z = packbf(__expf(b.x), __expf(b.y));
    u.w = packbf(__expf(b.z), __expf(b.w));
    *reinterpret_cast<uint4*>(g_xe + i) = u;
}

// ---------------- Pass 2: GEMM + log epilogue ----------------
__global__ __launch_bounds__(256, 4) void densesum_kernel(
    const float* __restrict__ W,   // [NSD][NIN][NSUM]
    float* __restrict__ O)         // [NSD][BDIM][NSUM]
{
    extern __shared__ __align__(16) char smem[];
    __shared__ float csums[NT];

    const int ct = blockIdx.x;     // 0..7
    const int sd = blockIdx.y;     // 0..255

    const __nv_bfloat16* Xe = g_xe + (size_t)sd * BDIM * NIN;
    const float* Wp = W + (size_t)sd * NIN * NSUM + ct * NT;
    float*       Op = O + (size_t)sd * BDIM * NSUM + ct * NT;

    const int t = threadIdx.x;
    if (t < NT) csums[t] = 0.f;

    const int warp = t >> 5, lane = t & 31;
    const int wm = warp >> 1, wn = warp & 1;
    const int l15 = lane & 15, lhi = lane >> 4;

    const uint32_t smb = s2u(smem);
    // A cp.async: chunk0 at (row t>>2, 16B-unit t&3); chunk1 = row+64 (derived)
    const int arow0 = t >> 2, ac40 = t & 3;
    // W cp.async / convert: thread owns (row t>>3, cols (t&7)*8 .. +7)
    const int wr  = t >> 3;          // 0..31
    const int wc8 = (t & 7) * 8;     // 0,8,..,56

    const uint32_t aln = (uint32_t)((wm * 32 + l15) * APITCH + lhi * 8) * 2;
    const uint32_t bln = (uint32_t)(l15 * BPITCH + wn * 32 + lhi * 8) * 2;
    const uint32_t bso = (uint32_t)(wr * BPITCH + wc8) * 2;   // Bs STS.128 offset

    // precomputed slot base addresses (manual rotation; no % in the loop)
    const uint32_t aA0 = smb + SM_A, aA1 = aA0 + ASTG, aA2 = aA1 + ASTG;
    const uint32_t wA0 = smb + SM_W, wA1 = wA0 + WSTG;
    const uint32_t bA0 = smb + SM_B, bA1 = bA0 + BSBUF;

    float acc[2][4][4];
    #pragma unroll
    for (int i = 0; i < 2; i++)
        #pragma unroll
        for (int j = 0; j < 4; j++)
            #pragma unroll
            for (int k = 0; k < 4; k++) acc[i][j][k] = 0.f;
    float csum[8];
    #pragma unroll
    for (int i = 0; i < 8; i++) csum[i] = 0.f;

    auto issue_a = [&](uint32_t aslot, int st) {
        const __nv_bfloat16* Xs = Xe + st * KC + (size_t)arow0 * NIN + ac40 * 8;
        const uint32_t d0 = aslot + (uint32_t)(arow0 * 80 + ac40 * 16);
        asm volatile("cp.async.cg.shared.global [%0], [%1], 16;"
                     :: "r"(d0), "l"(Xs));
        asm volatile("cp.async.cg.shared.global [%0], [%1], 16;"
                     :: "r"(d0 + 64 * 80), "l"(Xs + (size_t)64 * NIN));
    };
    auto issue_w = [&](uint32_t wslot, int st) {
        const float* Ws = Wp + (size_t)st * KC * NSUM + (size_t)wr * NSUM + wc8;
        asm volatile("cp.async.cg.shared.global [%0], [%1], 16;"
                     :: "r"(wslot + (uint32_t)(t * 16)), "l"(Ws));
        asm volatile("cp.async.cg.shared.global [%0], [%1], 16;"
                     :: "r"(wslot + (uint32_t)(4096 + t * 16)), "l"(Ws + 4));
    };

    // convert: W slot -> exp -> Bs buf + csum. Reads ONLY this thread's own
    // cp.async chunks (t*16, 4096+t*16) => own wait_group suffices.
    // Row-contiguous output: single STS.128 of 8 bf16.
    auto convert = [&](uint32_t wslot, uint32_t bbuf) {
        float4 v0, v1;
        asm volatile("ld.shared.v4.f32 {%0,%1,%2,%3}, [%4];"
                     : "=f"(v0.x), "=f"(v0.y), "=f"(v0.z), "=f"(v0.w)
                     : "r"(wslot + (uint32_t)(t * 16)));
        asm volatile("ld.shared.v4.f32 {%0,%1,%2,%3}, [%4];"
                     : "=f"(v1.x), "=f"(v1.y), "=f"(v1.z), "=f"(v1.w)
                     : "r"(wslot + (uint32_t)(4096 + t * 16)));
        float e0 = __expf(v0.x), e1 = __expf(v0.y), e2 = __expf(v0.z), e3 = __expf(v0.w);
        float e4 = __expf(v1.x), e5 = __expf(v1.y), e6 = __expf(v1.z), e7 = __expf(v1.w);
        csum[0] += e0; csum[1] += e1; csum[2] += e2; csum[3] += e3;
        csum[4] += e4; csum[5] += e5; csum[6] += e6; csum[7] += e7;
        asm volatile("st.shared.v4.b32 [%0], {%1,%2,%3,%4};"
                     :: "r"(bbuf + bso),
                        "r"(packbf(e0, e1)), "r"(packbf(e2, e3)),
                        "r"(packbf(e4, e5)), "r"(packbf(e6, e7)) : "memory");
    };

    // prologue: {A0}{W0}{A1}{W1}; wait_group 2 retires {A0},{W0}; convert(0).
    issue_a(aA0, 0);
    asm volatile("cp.async.commit_group;" ::: "memory");
    issue_w(wA0, 0);
    asm volatile("cp.async.commit_group;" ::: "memory");
    issue_a(aA1, 1);
    asm volatile("cp.async.commit_group;" ::: "memory");
    issue_w(wA1, 1);
    asm volatile("cp.async.commit_group;" ::: "memory");
    asm volatile("cp.async.wait_group 2;" ::: "memory");
    convert(wA0, bA0);

    // rotating slot registers: asl0 = slot(ch%3); wcur/bcur = slot(ch%2)
    uint32_t asl0 = aA0, asl1 = aA1, asl2 = aA2;
    uint32_t wcur = wA0, wnxt = wA1;
    uint32_t bcur = bA0, bnxt = bA1;

    #pragma unroll 2
    for (int ch = 0; ch < NCH; ch++) {
        // one barrier: publishes A(ch) (retired by all threads at iter ch-1's
        // wait) and Bs cur (written by convert(ch) in iter ch-1).
        __syncthreads();

        // distance-2 issues; always commit (exact ledger: 2 groups/iter)
        if (ch + 2 < NCH) issue_a(asl2, ch + 2);   // slot (ch+2)%3; reader MMA(ch-1) pre-barrier
        asm volatile("cp.async.commit_group;" ::: "memory");
        if (ch + 2 < NCH) issue_w(wcur, ch + 2);   // slot ch%2; prior reader convert(ch), same thread
        asm volatile("cp.async.commit_group;" ::: "memory");

        // retire {A(ch+1)},{W(ch+1)}; keep the two just-issued groups pending
        asm volatile("cp.async.wait_group 2;" ::: "memory");

        // convert NEXT chunk — overlaps this chunk's MMA stream below
        if (ch + 1 < NCH) convert(wnxt, bnxt);

        // MMA(ch): fragments via ldmatrix from asl0 + bcur
        #pragma unroll
        for (int ks = 0; ks < 2; ks++) {
            unsigned afr[2][4];
            #pragma unroll
            for (int mf = 0; mf < 2; mf++) {
                const uint32_t addr = asl0 + aln
                    + (uint32_t)(mf * 16 * APITCH * 2) + (uint32_t)(ks * 32);
                asm volatile(
                    "ldmatrix.sync.aligned.m8n8.x4.shared.b16 {%0,%1,%2,%3}, [%4];"
                    : "=r"(afr[mf][0]), "=r"(afr[mf][1]),
                      "=r"(afr[mf][2]), "=r"(afr[mf][3]) : "r"(addr));
            }
            unsigned bfr[2][4];
            #pragma unroll
            for (int np = 0; np < 2; np++) {
                const uint32_t addr = bcur + bln
                    + (uint32_t)(ks * 16 * BPITCH * 2) + (uint32_t)(np * 32);
                asm volatile(
                    "ldmatrix.sync.aligned.m8n8.x4.trans.shared.b16 {%0,%1,%2,%3}, [%4];"
                    : "=r"(bfr[np][0]), "=r"(bfr[np][1]),
                      "=r"(bfr[np][2]), "=r"(bfr[np][3]) : "r"(addr));
            }
            #pragma unroll
            for (int mf = 0; mf < 2; mf++)
                #pragma unroll
                for (int nf = 0; nf < 4; nf++) {
                    const int np = nf >> 1, sel = (nf & 1) * 2;
                    asm volatile(
                        "mma.sync.aligned.m16n8k16.row.col.f32.bf16.bf16.f32 "
                        "{%0,%1,%2,%3}, {%4,%5,%6,%7}, {%8,%9}, {%0,%1,%2,%3};\n"
                        : "+f"(acc[mf][nf][0]), "+f"(acc[mf][nf][1]),
                          "+f"(acc[mf][nf][2]), "+f"(acc[mf][nf][3])
                        : "r"(afr[mf][0]), "r"(afr[mf][1]),
                          "r"(afr[mf][2]), "r"(afr[mf][3]),
                          "r"(bfr[np][sel]), "r"(bfr[np][sel + 1]));
                }
        }

        // rotate slots: A advances by one; W/Bs toggle
        uint32_t tmp = asl0; asl0 = asl1; asl1 = asl2; asl2 = tmp;
        uint32_t tw = wcur; wcur = wnxt; wnxt = tw;
        uint32_t tb = bcur; bcur = bnxt; bnxt = tb;
    }

    // column-sum reduce: lanes {l, l^8, l^16, l^24} share the same col-group
    #pragma unroll
    for (int i = 0; i < 8; i++) {
        csum[i] += __shfl_xor_sync(0xffffffffu, csum[i], 8);
        csum[i] += __shfl_xor_sync(0xffffffffu, csum[i], 16);
    }
    if (lane < 8) {
        #pragma unroll
        for (int i = 0; i < 8; i++)
            atomicAdd(&csums[lane * 8 + i], csum[i]);
    }
    __syncthreads();
    if (t < NT) csums[t] = __logf(csums[t]);
    __syncthreads();

    // epilogue: out = log(P) - log(C[col]); vectorized STG.64
    const int g = lane >> 2, q = lane & 3;
    #pragma unroll
    for (int nf = 0; nf < 4; nf++) {
        const int c = wn * 32 + nf * 8 + q * 2;
        const float lc0 = csums[c];
        const float lc1 = csums[c + 1];
        #pragma unroll
        for (int mf = 0; mf < 2; mf++) {
            const int r0 = wm * 32 + mf * 16 + g;
            float2 v0, v1;
            v0.x = __logf(acc[mf][nf][0]) - lc0;
            v0.y = __logf(acc[mf][nf][1]) - lc1;
            v1.x = __logf(acc[mf][nf][2]) - lc0;
            v1.y = __logf(acc[mf][nf][3]) - lc1;
            *reinterpret_cast<float2*>(Op + (size_t)r0 * NSUM + c)       = v0;
            *reinterpret_cast<float2*>(Op + (size_t)(r0 + 8) * NSUM + c) = v1;
        }
    }
}

extern "C" void kernel_launch(void* const* d_in, const int* in_sizes, int n_in,
                              void* d_out, int out_size)
{
    const float* x    = (const float*)d_in[0];
    const float* accs = (const float*)d_in[1];
    if (n_in >= 2 && in_sizes[0] > in_sizes[1]) {
        const float* tmp = x; x = accs; accs = tmp;
    }
    cudaFuncSetAttribute(densesum_kernel,
                         cudaFuncAttributeMaxDynamicSharedMemorySize, SM_TOT);
    expx_kernel<<<(NSD * BDIM * NIN) / (8 * 256), 256>>>(x);
    dim3 grid(NSUM / NT, NSD);   // (8, 256)
    densesum_kernel<<<grid, 256, SM_TOT>>>(accs, (float*)d_out);
}

// round 17
// speedup vs baseline: 1.3913x; 1.3913x over previous
#include <cuda_runtime.h>
#include <cuda_bf16.h>
#include <cstdint>

// out[b,k] = log( sum_n exp(x[b,n]) * exp(acc[n,k]) ) - log( sum_n exp(acc[n,k]) )
// per (s,d): GEMM M=128, N=512, K=512.
// Pass 1: exp(X) -> bf16 scratch.
// Pass 2: HMMA GEMM. A: 3-stage bf16 ring, W: 2-stage fp32 ring, distance-2
// issue, retire one iter before the consuming barrier. One barrier/chunk;
// convert(ch+1) overlaps MMA(ch). 4 CTAs/SM.
// R17: R15 structure (dense-sector W mapping) + merged commit group/iter +
// derived A chunk-1 addressing. R16's strided 16B mapping reverted (sector
// amplification: L2 56%, dur +42%).

#define NSD     256
#define BDIM    128
#define NIN     512
#define NSUM    512
#define KC      32
#define NT      64
#define APITCH  40          // bf16/row (80B): LDSM conflict-free
#define BPITCH  72          // bf16/row (144B): LDSM conflict-free
#define NCH     (NIN/KC)    // 16
#define RINGA   3
#define RINGW   2
#define ASTG    (BDIM*APITCH*2)     // 10240 B
#define WSTG    (KC*NT*4)           // 8192 B
#define BSBUF   (KC*BPITCH*2)       // 4608 B
#define SM_A    0
#define SM_W    (RINGA*ASTG)                // 30720
#define SM_B    (SM_W + RINGW*WSTG)         // 47104
#define SM_TOT  (SM_B + 2*BSBUF)            // 56320

__device__ __nv_bfloat16 g_xe[(size_t)NSD * BDIM * NIN];   // 33.5MB scratch

__device__ __forceinline__ unsigned packbf(float a, float b) {
    __nv_bfloat162 h = __floats2bfloat162_rn(a, b);
    return *reinterpret_cast<unsigned const*>(&h);
}
__device__ __forceinline__ uint32_t s2u(const void* p) {
    uint32_t a;
    asm("{ .reg .u64 t; cvta.to.shared.u64 t, %1; cvt.u32.u64 %0, t; }" : "=r"(a) : "l"(p));
    return a;
}

// ---------------- Pass 1: Xe = bf16(exp(X)) ----------------
__global__ __launch_bounds__(256) void expx_kernel(const float* __restrict__ X) {
    const size_t i = ((size_t)blockIdx.x * blockDim.x + threadIdx.x) * 8;
    float4 a = *reinterpret_cast<const float4*>(X + i);
    float4 b = *reinterpret_cast<const float4*>(X + i + 4);
    uint4 u;
    u.x = packbf(__expf(a.x), __expf(a.y));
    u.y = packbf(__expf(a.z), __expf(a.w));
    u.z = packbf(__expf(b.x), __expf(b.y));
    u.w = packbf(__expf(b.z), __expf(b.w));
    *reinterpret_cast<uint4*>(g_xe + i) = u;
}

// ---------------- Pass 2: GEMM + log epilogue ----------------
__global__ __launch_bounds__(256, 4) void densesum_kernel(
    const float* __restrict__ W,   // [NSD][NIN][NSUM]
    float* __restrict__ O)         // [NSD][BDIM][NSUM]
{
    extern __shared__ __align__(16) char smem[];
    __shared__ float csums[NT];

    const int ct = blockIdx.x;     // 0..7
    const int sd = blockIdx.y;     // 0..255

    const __nv_bfloat16* Xe = g_xe + (size_t)sd * BDIM * NIN;
    const float* Wp = W + (size_t)sd * NIN * NSUM + ct * NT;
    float*       Op = O + (size_t)sd * BDIM * NSUM + ct * NT;

    const int t = threadIdx.x;
    if (t < NT) csums[t] = 0.f;

    const int warp = t >> 5, lane = t & 31;
    const int wm = warp >> 1, wn = warp & 1;
    const int l15 = lane & 15, lhi = lane >> 4;

    const uint32_t smb = s2u(smem);
    // A cp.async: chunk0 at (row t>>2, 16B unit t&3); chunk1 = row+64 (derived)
    const int arow0 = t >> 2, ac40 = t & 3;
    // W cp.async: dense per-instruction sectors — chunk j covers rows 16j..16j+15,
    // thread (row t>>4 + 16j, 16B unit t&15); per warp: 2 full 256B rows.
    const int wrow0 = t >> 4,         wc0 = t & 15;
    const int wrow1 = (t + 256) >> 4, wc1 = (t + 256) & 15;
    // convert/Bs mapping: thread owns cols bc..bc+3 of rows br and br+16
    const int br = t >> 4, bc = (t & 15) * 4;

    const uint32_t aln = (uint32_t)((wm * 32 + l15) * APITCH + lhi * 8) * 2;
    const uint32_t bln = (uint32_t)(l15 * BPITCH + wn * 32 + lhi * 8) * 2;

    // precomputed slot base addresses (manual rotation; no % in the loop)
    const uint32_t aA0 = smb + SM_A, aA1 = aA0 + ASTG, aA2 = aA1 + ASTG;
    const uint32_t wA0 = smb + SM_W, wA1 = wA0 + WSTG;
    const uint32_t bA0 = smb + SM_B, bA1 = bA0 + BSBUF;

    float acc[2][4][4];
    #pragma unroll
    for (int i = 0; i < 2; i++)
        #pragma unroll
        for (int j = 0; j < 4; j++)
            #pragma unroll
            for (int k = 0; k < 4; k++) acc[i][j][k] = 0.f;
    float csum[4] = {0.f, 0.f, 0.f, 0.f};

    auto issue_a = [&](uint32_t aslot, int st) {
        const __nv_bfloat16* Xs = Xe + st * KC + (size_t)arow0 * NIN + ac40 * 8;
        const uint32_t d0 = aslot + (uint32_t)(arow0 * 80 + ac40 * 16);
        asm volatile("cp.async.cg.shared.global [%0], [%1], 16;"
                     :: "r"(d0), "l"(Xs));
        asm volatile("cp.async.cg.shared.global [%0], [%1], 16;"
                     :: "r"(d0 + 64 * 80), "l"(Xs + (size_t)64 * NIN));
    };
    auto issue_w = [&](uint32_t wslot, int st) {
        const float* Ws = Wp + (size_t)st * KC * NSUM;
        asm volatile("cp.async.cg.shared.global [%0], [%1], 16;"
                     :: "r"(wslot + (uint32_t)(wrow0 * 256 + wc0 * 16)),
                        "l"(Ws + (size_t)wrow0 * NSUM + wc0 * 4));
        asm volatile("cp.async.cg.shared.global [%0], [%1], 16;"
                     :: "r"(wslot + (uint32_t)(wrow1 * 256 + wc1 * 16)),
                        "l"(Ws + (size_t)wrow1 * NSUM + wc1 * 4));
    };

    // convert: W slot -> exp -> Bs buf + csum. Reads ONLY this thread's own
    // cp.async chunks (t*16, 4096+t*16) => own wait_group suffices.
    auto convert = [&](uint32_t wslot, uint32_t bbuf) {
        #pragma unroll
        for (int j = 0; j < 2; j++) {
            float4 v;
            asm volatile("ld.shared.v4.f32 {%0,%1,%2,%3}, [%4];"
                         : "=f"(v.x), "=f"(v.y), "=f"(v.z), "=f"(v.w)
                         : "r"(wslot + (uint32_t)(j * 4096 + t * 16)));
            float e0 = __expf(v.x), e1 = __expf(v.y), e2 = __expf(v.z), e3 = __expf(v.w);
            csum[0] += e0; csum[1] += e1; csum[2] += e2; csum[3] += e3;
            asm volatile("st.shared.v2.b32 [%0], {%1,%2};"
                         :: "r"(bbuf + (uint32_t)(((br + 16 * j) * BPITCH + bc) * 2)),
                            "r"(packbf(e0, e1)), "r"(packbf(e2, e3)) : "memory");
        }
    };

    // prologue: groups {A0,W0}, {A1,W1}; wait_group 1 retires group0; convert(0).
    issue_a(aA0, 0);
    issue_w(wA0, 0);
    asm volatile("cp.async.commit_group;" ::: "memory");
    issue_a(aA1, 1);
    issue_w(wA1, 1);
    asm volatile("cp.async.commit_group;" ::: "memory");
    asm volatile("cp.async.wait_group 1;" ::: "memory");
    convert(wA0, bA0);

    // rotating slot registers: asl0 = slot(ch%3); wcur/bcur = slot(ch%2)
    uint32_t asl0 = aA0, asl1 = aA1, asl2 = aA2;
    uint32_t wcur = wA0, wnxt = wA1;
    uint32_t bcur = bA0, bnxt = bA1;

    #pragma unroll 2
    for (int ch = 0; ch < NCH; ch++) {
        // one barrier: publishes A(ch) (group retired by all threads at iter
        // ch-1's wait) and Bs cur (written by convert(ch) in iter ch-1).
        __syncthreads();

        // one merged group {A(ch+2), W(ch+2)}; always commit (exact ledger)
        if (ch + 2 < NCH) {
            issue_a(asl2, ch + 2);   // slot (ch+2)%3; prior reader MMA(ch-1) pre-barrier
            issue_w(wcur, ch + 2);   // slot ch%2; prior reader convert(ch), same thread
        }
        asm volatile("cp.async.commit_group;" ::: "memory");

        // retire group(ch+1): A(ch+1) (for next iter's barrier) and W(ch+1)
        asm volatile("cp.async.wait_group 1;" ::: "memory");

        // convert NEXT chunk — overlaps this chunk's MMA stream below
        if (ch + 1 < NCH) convert(wnxt, bnxt);

        // MMA(ch): fragments via ldmatrix from asl0 + bcur
        #pragma unroll
        for (int ks = 0; ks < 2; ks++) {
            unsigned afr[2][4];
            #pragma unroll
            for (int mf = 0; mf < 2; mf++) {
                const uint32_t addr = asl0 + aln
                    + (uint32_t)(mf * 16 * APITCH * 2) + (uint32_t)(ks * 32);
                asm volatile(
                    "ldmatrix.sync.aligned.m8n8.x4.shared.b16 {%0,%1,%2,%3}, [%4];"
                    : "=r"(afr[mf][0]), "=r"(afr[mf][1]),
                      "=r"(afr[mf][2]), "=r"(afr[mf][3]) : "r"(addr));
            }
            unsigned bfr[2][4];
            #pragma unroll
            for (int np = 0; np < 2; np++) {
                const uint32_t addr = bcur + bln
                    + (uint32_t)(ks * 16 * BPITCH * 2) + (uint32_t)(np * 32);
                asm volatile(
                    "ldmatrix.sync.aligned.m8n8.x4.trans.shared.b16 {%0,%1,%2,%3}, [%4];"
                    : "=r"(bfr[np][0]), "=r"(bfr[np][1]),
                      "=r"(bfr[np][2]), "=r"(bfr[np][3]) : "r"(addr));
            }
            #pragma unroll
            for (int mf = 0; mf < 2; mf++)
                #pragma unroll
                for (int nf = 0; nf < 4; nf++) {
                    const int np = nf >> 1, sel = (nf & 1) * 2;
                    asm volatile(
                        "mma.sync.aligned.m16n8k16.row.col.f32.bf16.bf16.f32 "
                        "{%0,%1,%2,%3}, {%4,%5,%6,%7}, {%8,%9}, {%0,%1,%2,%3};\n"
                        : "+f"(acc[mf][nf][0]), "+f"(acc[mf][nf][1]),
                          "+f"(acc[mf][nf][2]), "+f"(acc[mf][nf][3])
                        : "r"(afr[mf][0]), "r"(afr[mf][1]),
                          "r"(afr[mf][2]), "r"(afr[mf][3]),
                          "r"(bfr[np][sel]), "r"(bfr[np][sel + 1]));
                }
        }

        // rotate slots: A advances by one; W/Bs toggle
        uint32_t tmp = asl0; asl0 = asl1; asl1 = asl2; asl2 = tmp;
        uint32_t tw = wcur; wcur = wnxt; wnxt = tw;
        uint32_t tb = bcur; bcur = bnxt; bnxt = tb;
    }

    // column-sum reduce
    atomicAdd(&csums[bc + 0], csum[0]);
    atomicAdd(&csums[bc + 1], csum[1]);
    atomicAdd(&csums[bc + 2], csum[2]);
    atomicAdd(&csums[bc + 3], csum[3]);
    __syncthreads();
    if (t < NT) csums[t] = __logf(csums[t]);
    __syncthreads();

    // epilogue: out = log(P) - log(C[col]); vectorized STG.64
    const int g = lane >> 2, q = lane & 3;
    #pragma unroll
    for (int nf = 0; nf < 4; nf++) {
        const int c = wn * 32 + nf * 8 + q * 2;
        const float lc0 = csums[c];
        const float lc1 = csums[c + 1];
        #pragma unroll
        for (int mf = 0; mf < 2; mf++) {
            const int r0 = wm * 32 + mf * 16 + g;
            float2 v0, v1;
            v0.x = __logf(acc[mf][nf][0]) - lc0;
            v0.y = __logf(acc[mf][nf][1]) - lc1;
            v1.x = __logf(acc[mf][nf][2]) - lc0;
            v1.y = __logf(acc[mf][nf][3]) - lc1;
            *reinterpret_cast<float2*>(Op + (size_t)r0 * NSUM + c)       = v0;
            *reinterpret_cast<float2*>(Op + (size_t)(r0 + 8) * NSUM + c) = v1;
        }
    }
}

extern "C" void kernel_launch(void* const* d_in, const int* in_sizes, int n_in,
                              void* d_out, int out_size)
{
    const float* x    = (const float*)d_in[0];
    const float* accs = (const float*)d_in[1];
    if (n_in >= 2 && in_sizes[0] > in_sizes[1]) {
        const float* tmp = x; x = accs; accs = tmp;
    }
    cudaFuncSetAttribute(densesum_kernel,
                         cudaFuncAttributeMaxDynamicSharedMemorySize, SM_TOT);
    expx_kernel<<<(NSD * BDIM * NIN) / (8 * 256), 256>>>(x);
    dim3 grid(NSUM / NT, NSD);   // (8, 256)
    densesum_kernel<<<grid, 256, SM_TOT>>>(accs, (float*)d_out);
}